// round 17
// baseline (speedup 1.0000x reference)
#include <cuda_runtime.h>
#include <cuda_fp16.h>
#include <math.h>
#include <complex>
#include <cstring>
#include <cstdint>

// ============================================================================
// FullyConnectedTensorProduct, three-launch pipelined scheme (R15):
//   K1: prep for n in [0, Nh)  (+ wprep weight transform blocks)
//   K2: MIXED kernel: gemm tiles whose rows lie entirely in n < Nh  run
//       concurrently with prep blocks for n in [Nh, N)  -> prep overlaps GEMM
//   K3: gemm for the remaining tiles (incl. straddlers; prep fully done)
//   Math identical to R12-R14 (single fp16 term Ah*Wh) -> bit-identical out.
// ============================================================================

#define NPATHS 11

// ---- A scratch: tiles of 64 rows x 128 u fp16 (8192 halves, swizzled) ------
#define AT_LO0   0
#define AT_LO1   960
#define AT_LO2   4800
#define AT_TOT   11200
__device__ __align__(16) __half g_A[(size_t)AT_TOT * 8192];
__device__ __align__(16) __half g_B[NPATHS][16384];   // weights, fp16 hi

// ---- GEMM smem layout (bytes): A double-buf + B double-buf -----------------
#define A0_OFF    0
#define A1_OFF    16384
#define B0_OFF    32768
#define B1_OFF    65536
#define SMEM_TOTAL 98304
#define EPI_OFF   0

#define WPREP_BLOCKS 44

struct Params {
    float C[363];
    int4  cmap[115];    // ALL-paths order p0..p10
};

struct LoCfg { int np; int gid[4]; };
__device__ __constant__ const LoCfg kCfg[3] = {
    {3, {0,4,9,0}},
    {4, {1,3,6,8}},
    {4, {2,5,7,10}},
};

// ---- PTX helpers -----------------------------------------------------------
__device__ __forceinline__ uint32_t smem_u32(const void* p) {
    uint32_t a;
    asm("{ .reg .u64 t; cvta.to.shared.u64 t, %1; cvt.u32.u64 %0, t; }"
        : "=r"(a) : "l"(p));
    return a;
}
__device__ __forceinline__ void cpasync16(uint32_t dst, const void* src) {
    asm volatile("cp.async.cg.shared.global [%0], [%1], 16;"
                 :: "r"(dst), "l"(src) : "memory");
}
#define LDSM4(R, ADDR)                                                        \
    asm volatile("ldmatrix.sync.aligned.m8n8.x4.shared.b16 "                  \
                 "{%0,%1,%2,%3}, [%4];"                                       \
                 : "=r"((R)[0]), "=r"((R)[1]), "=r"((R)[2]), "=r"((R)[3])     \
                 : "r"(ADDR))
#define MMA(D, A, B0, B1)                                                     \
    asm volatile("mma.sync.aligned.m16n8k16.row.col.f32.f16.f16.f32 "         \
                 "{%0,%1,%2,%3}, {%4,%5,%6,%7}, {%8,%9}, {%0,%1,%2,%3};"      \
                 : "+f"((D)[0]), "+f"((D)[1]), "+f"((D)[2]), "+f"((D)[3])     \
                 : "r"((A)[0]), "r"((A)[1]), "r"((A)[2]), "r"((A)[3]),        \
                   "r"(B0), "r"(B1))

__device__ __host__ __forceinline__ uint32_t swz(int row, int u) {
    return (uint32_t)row * 256u
         + (uint32_t)(((u >> 3) ^ (row & 7)) << 4)
         + (uint32_t)((u & 7) * 2);
}

// ============================================================================
// prep body (aprep): 8 n's per block starting at n0, limited to n < nEnd
// ============================================================================
#define PREP_PATH(CB, D1, DLP, TB, XS) {                                      \
    const int mbase = n * (DLP);                                              \
    _Pragma("unroll")                                                         \
    for (int k = 0; k < (DLP); k++) {                                         \
        float s0 = 0.f, s1 = 0.f, s2 = 0.f, s3 = 0.f;                         \
        _Pragma("unroll")                                                     \
        for (int i = 0; i < (D1); i++) {                                      \
            float cc = cn[(CB) + i * (DLP) + k];                              \
            s0 += XS[0 * (D1) + i] * cc;                                      \
            s1 += XS[1 * (D1) + i] * cc;                                      \
            s2 += XS[2 * (D1) + i] * cc;                                      \
            s3 += XS[3 * (D1) + i] * cc;                                      \
        }                                                                     \
        __half2 pa = __floats2half2_rn(s0, s1);                               \
        __half2 pb = __floats2half2_rn(s2, s3);                               \
        int mm = mbase + k;                                                   \
        int tt = mm >> 6, r = mm & 63;                                        \
        *(uint2*)((char*)g_A + ((size_t)((TB) + tt) << 14) + swz(r, u0)) =    \
            make_uint2(*(uint32_t*)&pa, *(uint32_t*)&pb);                     \
    } }

__device__ __forceinline__ void prep_body(
    int n0, int nEnd, const float* __restrict__ x1,
    const float* __restrict__ x2, const Params& P)
{
    __shared__ float ct[8][116];
    const int tid = threadIdx.x;

    for (int t = tid; t < 8 * 115; t += 256) {
        int nl = t / 115, e = t - nl * 115;
        int n = n0 + nl;
        float s = 0.f;
        if (n < nEnd) {
            int4 m = P.cmap[e];
            const float* xr = x2 + (size_t)n * 9 + m.w;
            for (int j = 0; j < m.y; j++) s += P.C[m.x + j * m.z] * xr[j];
        }
        ct[nl][e] = s;
    }
    __syncthreads();

    const int nl = tid >> 5, q = tid & 31;
    const int n = n0 + nl;
    if (n >= nEnd) return;
    const int u0 = 4 * q;

    const float* xr = x1 + (size_t)n * 1152;
    float x0v[4], x1v[12], x2v[20];
    *(float4*)x0v = *(const float4*)(xr + u0);
    #pragma unroll
    for (int i = 0; i < 3; i++)
        *(float4*)(x1v + 4 * i) = *(const float4*)(xr + 128 + 12 * q + 4 * i);
    #pragma unroll
    for (int i = 0; i < 5; i++)
        *(float4*)(x2v + 4 * i) = *(const float4*)(xr + 512 + 20 * q + 4 * i);

    const float* cn = ct[nl];
    PREP_PATH( 0, 1, 1, AT_LO0 +    0, x0v)
    PREP_PATH( 1, 1, 3, AT_LO1 +    0, x0v)
    PREP_PATH( 4, 1, 5, AT_LO2 +    0, x0v)
    PREP_PATH( 9, 3, 3, AT_LO1 +  960, x1v)
    PREP_PATH(18, 3, 1, AT_LO0 +  320, x1v)
    PREP_PATH(21, 3, 5, AT_LO2 + 1600, x1v)
    PREP_PATH(36, 3, 3, AT_LO1 + 1920, x1v)
    PREP_PATH(45, 5, 5, AT_LO2 + 3200, x2v)
    PREP_PATH(70, 5, 3, AT_LO1 + 2880, x2v)
    PREP_PATH(85, 5, 1, AT_LO0 +  640, x2v)
    PREP_PATH(90, 5, 5, AT_LO2 + 4800, x2v)
}

// ============================================================================
// K1: prep for n < Nh, plus wprep blocks
// ============================================================================
__global__ __launch_bounds__(256)
void prep1_kernel(const float* __restrict__ x1, const float* __restrict__ x2,
                  const float* __restrict__ wt, int Nh, int NA,
                  const __grid_constant__ Params P)
{
    const int tid = threadIdx.x;
    if ((int)blockIdx.x >= NA) {
        const int base = ((int)blockIdx.x - NA) * 4096;
        #pragma unroll
        for (int it = 0; it < 16; it++) {
            int idx = base + it * 256 + tid;
            int gid = idx >> 14;
            int e   = idx & 16383;
            int u = e >> 7, w = e & 127;
            g_B[gid][swz(w, u) >> 1] =
                __float2half_rn(wt[(size_t)gid * 16384 + u * 128 + w]);
        }
        return;
    }
    prep_body((int)blockIdx.x * 8, Nh, x1, x2, P);
}

// ============================================================================
// GEMM body (unchanged math), templated on LO
// ============================================================================
template<int LO>
__device__ __forceinline__ void body(
    int mt_idx, float* __restrict__ out, int Ntot, char* smem)
{
    constexpr int DL  = 2 * LO + 1;
    constexpr int NP  = (LO == 0) ? 3 : 4;
    constexpr int OB  = (LO == 0) ? 0 : (LO == 1) ? 128 : 512;
    constexpr int ATB = (LO == 0) ? AT_LO0 : (LO == 1) ? AT_LO1 : AT_LO2;
    constexpr int ATS = (LO == 0) ? 320 : (LO == 1) ? 960 : 1600;

    const uint32_t sb = smem_u32(smem);
    const int tid  = threadIdx.x;
    const int wid  = tid >> 5;
    const int lane = tid & 31;

    const int m0 = mt_idx * 64;
    const int n_lo = m0 / DL;
    int n_hi = (m0 + 63) / DL;
    if (n_hi > Ntot - 1) n_hi = Ntot - 1;
    const int n_count = n_hi - n_lo + 1;

    auto loadStage = [&](int pi, int buf) {
        const char* asrc = (const char*)g_A
                         + ((size_t)(ATB + pi * ATS + mt_idx) << 14);
        uint32_t ad = sb + (buf ? A1_OFF : A0_OFF);
        for (int c = tid; c < 1024; c += 256)
            cpasync16(ad + c * 16, asrc + c * 16);
        const int gid = kCfg[LO].gid[pi];
        uint32_t bd = sb + (buf ? B1_OFF : B0_OFF);
        for (int c = tid; c < 2048; c += 256)
            cpasync16(bd + c * 16, (const char*)g_B[gid] + c * 16);
        asm volatile("cp.async.commit_group;" ::: "memory");
    };
    loadStage(0, 0);

    const int mrow0 = (wid >> 2) * 32;
    const int ncol0 = (wid & 3) * 32;
    const int lrow  = lane & 15;
    const int khalf = lane >> 4;

    uint32_t aRow[2]; int a7[2];
    #pragma unroll
    for (int mt = 0; mt < 2; mt++) {
        int r = mrow0 + mt * 16 + lrow;
        aRow[mt] = (uint32_t)r * 256u;
        a7[mt] = r & 7;
    }
    uint32_t bRow[2]; int b7[2];
    #pragma unroll
    for (int p = 0; p < 2; p++) {
        int r = ncol0 + p * 16 + lrow;
        bRow[p] = (uint32_t)r * 256u;
        b7[p] = r & 7;
    }

    float acc[2][4][4];
    #pragma unroll
    for (int i = 0; i < 2; i++)
        #pragma unroll
        for (int j = 0; j < 4; j++)
            #pragma unroll
            for (int c = 0; c < 4; c++) acc[i][j][c] = 0.f;

    #pragma unroll
    for (int pi = 0; pi < NP; pi++) {
        asm volatile("cp.async.wait_group 0;" ::: "memory");
        __syncthreads();
        if (pi + 1 < NP) loadStage(pi + 1, (pi + 1) & 1);

        const uint32_t abase = sb + ((pi & 1) ? A1_OFF : A0_OFF);
        const uint32_t bbase = sb + ((pi & 1) ? B1_OFF : B0_OFF);
        #pragma unroll 1
        for (int ks = 0; ks < 8; ks++) {
            const int ch = 2 * ks + khalf;
            uint32_t ah[2][4], bh[2][4];
            #pragma unroll
            for (int mt = 0; mt < 2; mt++)
                LDSM4(ah[mt], abase + aRow[mt] + (uint32_t)((ch ^ a7[mt]) << 4));
            #pragma unroll
            for (int p = 0; p < 2; p++)
                LDSM4(bh[p], bbase + bRow[p] + (uint32_t)((ch ^ b7[p]) << 4));
            #pragma unroll
            for (int mt = 0; mt < 2; mt++)
                #pragma unroll
                for (int p = 0; p < 2; p++) {
                    MMA(acc[mt][2*p],   ah[mt], bh[p][0], bh[p][2]);
                    MMA(acc[mt][2*p+1], ah[mt], bh[p][1], bh[p][3]);
                }
        }
    }

    __syncthreads();
    float* sepi = (float*)(smem + EPI_OFF);
    {
        const int arow = lane >> 2;
        const int acol = (lane & 3) * 2;
        #pragma unroll
        for (int mt = 0; mt < 2; mt++)
            #pragma unroll
            for (int nt = 0; nt < 4; nt++)
                #pragma unroll
                for (int c = 0; c < 4; c++) {
                    int r = mrow0 + mt * 16 + arow + ((c >> 1) << 3);
                    int w = ncol0 + nt * 8 + acol + (c & 1);
                    sepi[w * 68 + r] = acc[mt][nt][c];
                }
    }
    __syncthreads();

    constexpr int WDL = 128 * DL;
    const int tot = n_count * WDL;
    for (int e = tid; e < tot; e += 256) {
        int ni = e / WDL, o = e - ni * WDL;
        int wq = o / DL, k = o - wq * DL;
        int n = n_lo + ni;
        int r = n * DL + k - m0;
        if (n < Ntot && r >= 0 && r < 64)
            out[(size_t)n * 1152 + OB + o] = sepi[wq * 68 + r];
    }
}

// ============================================================================
// K2: mixed kernel — gemm tiles (first-half) + prep blocks (second-half n)
// ============================================================================
__global__ __launch_bounds__(256, 2)
void mix_kernel(float* __restrict__ out,
                const float* __restrict__ x1, const float* __restrict__ x2,
                int Ntot, int Nh, int gA0, int gA01, int G1,
                const __grid_constant__ Params P)
{
    extern __shared__ char smem[];
    const int b = blockIdx.x;
    if (b < G1) {
        if (b < gA0)        body<0>(b,        out, Ntot, smem);
        else if (b < gA01)  body<1>(b - gA0,  out, Ntot, smem);
        else                body<2>(b - gA01, out, Ntot, smem);
    } else {
        prep_body(Nh + (b - G1) * 8, Ntot, x1, x2, P);
    }
}

// ============================================================================
// K3: remaining gemm tiles (mt >= mtA[lo])
// ============================================================================
__global__ __launch_bounds__(256, 2)
void gemm2_kernel(float* __restrict__ out, int Ntot,
                  int c0, int c01, int mA0, int mA1, int mA2)
{
    extern __shared__ char smem[];
    const int b = blockIdx.x;
    if (b < c0)        body<0>(mA0 + b,        out, Ntot, smem);
    else if (b < c01)  body<1>(mA1 + b - c0,   out, Ntot, smem);
    else               body<2>(mA2 + b - c01,  out, Ntot, smem);
}

// ============================================================================
// Host: Wigner-3j construction (fp64, identical math to the reference)
// ============================================================================
typedef std::complex<double> cd;

static double factd(int n) { double r = 1; for (int i = 2; i <= n; i++) r *= i; return r; }

static double su2cg(int j1, int m1, int j2, int m2, int j3, int m3) {
    if (m3 != m1 + m2) return 0.0;
    int vmin = -j1 + j2 + m3; if (-j1 + m1 > vmin) vmin = -j1 + m1; if (0 > vmin) vmin = 0;
    int vmax = j2 + j3 + m1; if (j3 - j1 + j2 < vmax) vmax = j3 - j1 + j2; if (j3 + m3 < vmax) vmax = j3 + m3;
    if (vmax < vmin) return 0.0;
    double pref = (2.0 * j3 + 1.0) *
        (factd(j3 + j1 - j2) * factd(j3 - j1 + j2) * factd(j1 + j2 - j3) *
         factd(j3 + m3) * factd(j3 - m3)) /
        (factd(j1 + j2 + j3 + 1) * factd(j1 - m1) * factd(j1 + m1) *
         factd(j2 - m2) * factd(j2 + m2));
    double S = 0.0;
    for (int v = vmin; v <= vmax; v++) {
        int par = v + j2 + m2;
        double sgn = (((par % 2) + 2) % 2) ? -1.0 : 1.0;
        S += sgn * (factd(j2 + j3 + m1 - v) * factd(j1 - m1 + v)) /
             (factd(v) * factd(j3 - j1 + j2 - v) * factd(j3 + m3 - v) *
              factd(v + j1 - j2 - m3));
    }
    return sqrt(pref) * S;
}

static void calcq(int l, cd q[5][5]) {
    for (int a = 0; a < 5; a++) for (int b = 0; b < 5; b++) q[a][b] = cd(0, 0);
    const double s2 = 1.0 / sqrt(2.0);
    for (int m = -l; m < 0; m++) {
        q[l + m][l - m] = cd(s2, 0);
        q[l + m][l + m] = cd(0, -s2);
    }
    q[l][l] = cd(1, 0);
    for (int m = 1; m <= l; m++) {
        double sg = (m % 2) ? -1.0 : 1.0;
        q[l + m][l + m] = cd(sg * s2, 0);
        q[l + m][l - m] = cd(0, sg * s2);
    }
    cd f = (l == 0) ? cd(1, 0) : (l == 1) ? cd(0, -1) : cd(-1, 0); // (-i)^l
    for (int a = 0; a < 5; a++) for (int b = 0; b < 5; b++) q[a][b] *= f;
}

static void calc_w3j(int l1, int l2, int l3, double* outv) {
    int d1 = 2 * l1 + 1, d2 = 2 * l2 + 1, d3 = 2 * l3 + 1;
    double C[5][5][5];
    memset(C, 0, sizeof(C));
    for (int m1 = -l1; m1 <= l1; m1++)
        for (int m2 = -l2; m2 <= l2; m2++) {
            int m3 = m1 + m2;
            if (m3 >= -l3 && m3 <= l3)
                C[m1 + l1][m2 + l2][m3 + l3] = su2cg(l1, m1, l2, m2, l3, m3);
        }
    cd Q1[5][5], Q2[5][5], Q3[5][5];
    calcq(l1, Q1); calcq(l2, Q2); calcq(l3, Q3);
    static cd Cc[5][5][5];
    for (int j = 0; j < d1; j++)
        for (int l = 0; l < d2; l++)
            for (int m = 0; m < d3; m++) {
                cd s(0, 0);
                for (int i = 0; i < d1; i++)
                    for (int k = 0; k < d2; k++)
                        for (int n = 0; n < d3; n++)
                            s += Q1[i][j] * Q2[k][l] * std::conj(Q3[n][m]) * C[i][k][n];
                Cc[j][l][m] = s;
            }
    double nr = 0, ni = 0;
    for (int j = 0; j < d1; j++)
        for (int l = 0; l < d2; l++)
            for (int m = 0; m < d3; m++) {
                nr += Cc[j][l][m].real() * Cc[j][l][m].real();
                ni += Cc[j][l][m].imag() * Cc[j][l][m].imag();
            }
    bool useR = sqrt(nr) >= sqrt(ni);
    double nrm = sqrt(useR ? nr : ni);
    for (int j = 0; j < d1; j++)
        for (int l = 0; l < d2; l++)
            for (int m = 0; m < d3; m++)
                outv[(j * d2 + l) * d3 + m] =
                    (useR ? Cc[j][l][m].real() : Cc[j][l][m].imag()) / nrm;
}

static void build_params(Params& P) {
    static const int L1[NPATHS]   = {0,0,0,1,1,1,1,2,2,2,2};
    static const int L2[NPATHS]   = {0,1,2,0,1,1,2,0,1,2,2};
    static const int LOA[NPATHS]  = {0,1,2,1,0,2,1,2,1,0,2};
    static const int cof3[NPATHS] = {0,1,10,35,44,53,98,143,168,213,238};
    static const int x2off[3] = {0, 1, 4};
    const double pw[3] = { sqrt(1.0/384.0), sqrt(3.0/512.0), sqrt(5.0/512.0) };

    for (int p = 0; p < NPATHS; p++) {
        int d1 = 2*L1[p] + 1, d2 = 2*L2[p] + 1, d3 = 2*LOA[p] + 1;
        double buf[125];
        calc_w3j(L1[p], L2[p], LOA[p], buf);
        for (int idx = 0; idx < d1*d2*d3; idx++)
            P.C[cof3[p] + idx] = (float)(buf[idx] * pw[LOA[p]]);
    }
    int ci = 0;
    for (int p = 0; p < NPATHS; p++) {
        int d1 = 2*L1[p] + 1, d2 = 2*L2[p] + 1, d3 = 2*LOA[p] + 1;
        for (int i = 0; i < d1; i++)
            for (int k = 0; k < d3; k++)
                P.cmap[ci++] = make_int4(cof3[p] + i*d2*d3 + k, d2, d3,
                                         x2off[L2[p]]);
    }
}

extern "C" void kernel_launch(void* const* d_in, const int* in_sizes, int n_in,
                              void* d_out, int out_size)
{
    const float* x1  = (const float*)d_in[0];
    const float* x2  = (const float*)d_in[1];
    const float* wt  = (const float*)d_in[2];
    float*       out = (float*)d_out;
    const int N = in_sizes[0] / 1152;

    Params P;
    build_params(P);

    cudaFuncSetAttribute(mix_kernel,
                         cudaFuncAttributeMaxDynamicSharedMemorySize, SMEM_TOTAL);
    cudaFuncSetAttribute(gemm2_kernel,
                         cudaFuncAttributeMaxDynamicSharedMemorySize, SMEM_TOTAL);

    // split point (8-aligned, within [0, N])
    int Nh = ((N / 2) + 7) & ~7;
    if (Nh > N) Nh = N;

    // per-lo totals and first-half tile counts
    int T[3], mA[3];
    for (int lo = 0; lo < 3; lo++) {
        int DL = 2 * lo + 1;
        T[lo] = (N * DL + 63) / 64;
        long nd = (long)Nh * DL - 64;
        int a = (nd < 0) ? 0 : (int)(nd / 64) + 1;   // tiles with n_hi < Nh
        if (a > T[lo]) a = T[lo];
        mA[lo] = a;
    }
    const int G1 = mA[0] + mA[1] + mA[2];
    const int P2 = (N - Nh + 7) / 8;

    // K1: prep first half + wprep
    prep1_kernel<<<Nh / 8 + WPREP_BLOCKS, 256>>>(x1, x2, wt, Nh,
                                                 Nh / 8, P);
    // K2: gemm(first-half tiles) || prep(second half)
    if (G1 + P2 > 0)
        mix_kernel<<<G1 + P2, 256, SMEM_TOTAL>>>(out, x1, x2, N, Nh,
                                                 mA[0], mA[0] + mA[1], G1, P);
    // K3: remaining gemm tiles
    const int c0 = T[0] - mA[0], c1 = T[1] - mA[1], c2 = T[2] - mA[2];
    if (c0 + c1 + c2 > 0)
        gemm2_kernel<<<c0 + c1 + c2, 256, SMEM_TOTAL>>>(out, N,
                                                        c0, c0 + c1,
                                                        mA[0], mA[1], mA[2]);
}